// round 2
// baseline (speedup 1.0000x reference)
#include <cuda_runtime.h>
#include <cstdint>

// CRF Viterbi decode: B=128, T=1024, K=128.
// One CTA per batch element. Forward pass: value-only max-plus recurrence
// (transitions in registers, state in SMEM, logits staged via cp.async).
// State history -> 64MB device scratch. Backtrack recomputes the single
// needed argmax column per step from SMEM-staged state blocks, with exact
// first-index tie-breaking (matches jnp.argmax). Output = one-hot f32.

#define BB 128
#define TT 1024
#define KK 128
#define TC_STRIDE 132         // padded row stride for conflict-free column access
#define NTHREADS 256

// 64 MB state-history scratch (device global: allocation-free per harness rules)
__device__ float g_state[(size_t)BB * TT * KK];

struct SmemLayout {
    float transC[KK * TC_STRIDE];   // trans transposed: transC[j*132 + i] = T[i][j]
    float state[KK];                // current Viterbi state
    float part[KK];                 // partial max from half h=1
    float logit[2][8][KK];          // double-buffered logit staging (8 steps/block)
    float block[64 * KK];           // backtrack state-row staging (64 rows)
    int   tags[TT];
    int   lasttag;
};

__device__ __forceinline__ unsigned smem_u32(const void* p) {
    return (unsigned)__cvta_generic_to_shared(p);
}
__device__ __forceinline__ void cp_async16(unsigned dst, const void* src) {
    asm volatile("cp.async.cg.shared.global [%0], [%1], 16;" :: "r"(dst), "l"(src));
}
__device__ __forceinline__ void cp_commit() {
    asm volatile("cp.async.commit_group;");
}
// Warp-wide float max via butterfly shuffles (f32 redux not available on this target)
__device__ __forceinline__ float warp_max_f32(float v) {
    #pragma unroll
    for (int ofs = 16; ofs > 0; ofs >>= 1)
        v = fmaxf(v, __shfl_xor_sync(0xffffffffu, v, ofs));
    return v;
}

__global__ void __launch_bounds__(NTHREADS, 1)
crf_viterbi_kernel(const float* __restrict__ logits,
                   const int*   __restrict__ lens,
                   const float* __restrict__ trans,
                   float*       __restrict__ out)
{
    extern __shared__ char smraw[];
    SmemLayout& s = *reinterpret_cast<SmemLayout*>(smraw);

    const int b    = blockIdx.x;
    const int tid  = threadIdx.x;
    const int j    = tid & (KK - 1);   // output column
    const int h    = tid >> 7;         // which half of i-range [0,64) / [64,128)
    const int lane = tid & 31;
    const int len  = lens[b];

    // ---- transC (column-major copy of transitions, padded, for backtrack) ----
    for (int idx = tid; idx < KK * KK; idx += NTHREADS) {
        int i  = idx >> 7;
        int jj = idx & (KK - 1);
        s.transC[jj * TC_STRIDE + i] = trans[idx];
    }

    // ---- transitions for this thread's (j, h) into registers ----
    float treg[64];
    #pragma unroll
    for (int m = 0; m < 64; ++m)
        treg[m] = trans[(h * 64 + m) * KK + j];

    // ---- init state = logits[b, 0, :] ----
    if (h == 0) {
        float v = logits[((size_t)b * TT) * KK + j];
        s.state[j] = v;
        g_state[((size_t)b * TT) * KK + j] = v;
    }

    // ---- prologue: stage logit block 0 (rows t=1..8) into buffer 0 ----
    {
        int row = 1 + (tid >> 5);
        if (row > TT - 1) row = TT - 1;
        const float* src = logits + ((size_t)b * TT + row) * KK + (tid & 31) * 4;
        cp_async16(smem_u32(&s.logit[0][tid >> 5][(tid & 31) * 4]), src);
        cp_commit();
    }
    __syncthreads();

    const float* statebase = s.state + h * 64;

    // ================= forward pass (value-only) =================
    for (int t = 1; t < len; ++t) {
        int rel = t - 1;
        if ((rel & 7) == 0) {
            // stage next block, then ensure current block landed
            int g = rel >> 3;
            int base = 1 + (g + 1) * 8;
            int row = base + (tid >> 5);
            if (row > TT - 1) row = TT - 1;
            const float* src = logits + ((size_t)b * TT + row) * KK + (tid & 31) * 4;
            cp_async16(smem_u32(&s.logit[(g + 1) & 1][tid >> 5][(tid & 31) * 4]), src);
            cp_commit();
            asm volatile("cp.async.wait_group 1;");
            __syncthreads();
        }

        float a0 = -3.4e38f, a1 = -3.4e38f, a2 = -3.4e38f, a3 = -3.4e38f;
        #pragma unroll
        for (int q = 0; q < 16; ++q) {
            float4 st = *reinterpret_cast<const float4*>(statebase + 4 * q);
            a0 = fmaxf(a0, st.x + treg[4 * q + 0]);
            a1 = fmaxf(a1, st.y + treg[4 * q + 1]);
            a2 = fmaxf(a2, st.z + treg[4 * q + 2]);
            a3 = fmaxf(a3, st.w + treg[4 * q + 3]);
        }
        float best = fmaxf(fmaxf(a0, a1), fmaxf(a2, a3));

        if (h == 1) s.part[j] = best;
        __syncthreads();
        if (h == 0) {
            float v = fmaxf(best, s.part[j]) + s.logit[(rel >> 3) & 1][rel & 7][j];
            s.state[j] = v;
            g_state[((size_t)b * TT + t) * KK + j] = v;
        }
        __syncthreads();
    }
    asm volatile("cp.async.wait_all;");

    // ---- last tag = argmax_j final state (first-index tie-break) ----
    if (tid == 0) {
        float bv = s.state[0];
        int bi = 0;
        for (int i = 1; i < KK; ++i) {
            float v = s.state[i];
            if (v > bv) { bv = v; bi = i; }
        }
        s.lasttag = bi;
    }
    __syncthreads();
    const int lt = s.lasttag;

    // tail fill: tags[t] = last_tag for t >= len-1
    for (int t = len - 1 + tid; t < TT; t += NTHREADS) s.tags[t] = lt;

    // ================= backtrack (recompute bp column per step) =================
    int cur = lt;
    for (int hi = len - 2; hi >= 0; hi -= 64) {
        int lo = hi - 63;
        if (lo < 0) lo = 0;
        int n = (hi - lo + 1) * KK;
        const float* src = g_state + ((size_t)b * TT + lo) * KK;
        for (int idx = tid * 4; idx < n; idx += NTHREADS * 4)
            *reinterpret_cast<float4*>(&s.block[idx]) =
                *reinterpret_cast<const float4*>(src + idx);
        __syncthreads();

        if (tid < 32) {
            for (int t = hi; t >= lo; --t) {
                float4 sv = *reinterpret_cast<const float4*>(
                    &s.block[(t - lo) * KK + 4 * lane]);
                float4 tv = *reinterpret_cast<const float4*>(
                    &s.transC[cur * TC_STRIDE + 4 * lane]);
                float s0 = sv.x + tv.x;
                float s1 = sv.y + tv.y;
                float s2 = sv.z + tv.z;
                float s3 = sv.w + tv.w;
                float m = fmaxf(fmaxf(s0, s1), fmaxf(s2, s3));
                float g = warp_max_f32(m);
                // first-index tie-break: descending predicated writes, then min
                unsigned cand = 0x7fffffffu;
                if (s3 == g) cand = 4 * lane + 3;
                if (s2 == g) cand = 4 * lane + 2;
                if (s1 == g) cand = 4 * lane + 1;
                if (s0 == g) cand = 4 * lane + 0;
                cur = (int)__reduce_min_sync(0xffffffffu, cand);
                if (lane == 0) s.tags[t] = cur;
            }
        }
        __syncthreads();
    }
    __syncthreads();  // covers len==1 path (no backtrack barrier executed)

    // ================= one-hot output =================
    const int w = tid >> 5;  // warp id: warp w writes rows t = w + 8*it (coalesced)
    float* ob = out + (size_t)b * TT * KK;
    for (int it = 0; it < TT / 8; ++it) {
        int t = it * 8 + w;
        int tg = s.tags[t];
        float4 v;
        v.x = (tg == 4 * lane + 0) ? 1.0f : 0.0f;
        v.y = (tg == 4 * lane + 1) ? 1.0f : 0.0f;
        v.z = (tg == 4 * lane + 2) ? 1.0f : 0.0f;
        v.w = (tg == 4 * lane + 3) ? 1.0f : 0.0f;
        *reinterpret_cast<float4*>(ob + (size_t)t * KK + 4 * lane) = v;
    }
}

extern "C" void kernel_launch(void* const* d_in, const int* in_sizes, int n_in,
                              void* d_out, int out_size) {
    const float* logits = (const float*)d_in[0];
    const int*   lens   = (const int*)d_in[1];
    const float* trans  = (const float*)d_in[2];
    float*       out    = (float*)d_out;

    cudaFuncSetAttribute(crf_viterbi_kernel,
                         cudaFuncAttributeMaxDynamicSharedMemorySize,
                         (int)sizeof(SmemLayout));
    crf_viterbi_kernel<<<BB, NTHREADS, sizeof(SmemLayout)>>>(logits, lens, trans, out);
}

// round 3
// speedup vs baseline: 1.1562x; 1.1562x over previous
#include <cuda_runtime.h>
#include <cstdint>

// CRF Viterbi decode: B=128, T=1024, K=128. One CTA (512 threads) per batch.
// Forward: value-only max-plus, transitions packed f32x2 in registers,
// add.rn.f32x2 + scalar FMNMX; state in SMEM; logits cp.async double-buffered.
// State history -> 64MB device scratch. Backtrack: warp 0 recomputes the one
// needed argmax column per step using u32-monotone float mapping + integer
// REDUX (exact first-index tie-break, matches jnp.argmax). One-hot f32 out.

#define BB 128
#define TT 1024
#define KK 128
#define TC_STRIDE 132
#define NTHREADS 512

// 64 MB state-history scratch (device global: allocation-free per harness rules)
__device__ float g_state[(size_t)BB * TT * KK];

struct __align__(16) SmemLayout {
    float transC[KK * TC_STRIDE];   // transC[j*132 + i] = T[i][j] (backtrack)
    float state[KK];                // current Viterbi state
    float part[4][KK];              // per-quarter partial maxima
    float logit[2][16][KK];         // double-buffered logit staging (16 steps)
    float block[64 * KK];           // backtrack state-row staging (64 rows)
    int   tags[TT];
    int   lasttag;
};

__device__ __forceinline__ unsigned smem_u32(const void* p) {
    return (unsigned)__cvta_generic_to_shared(p);
}
__device__ __forceinline__ void cp_async16(unsigned dst, const void* src) {
    asm volatile("cp.async.cg.shared.global [%0], [%1], 16;" :: "r"(dst), "l"(src));
}
__device__ __forceinline__ void cp_commit() {
    asm volatile("cp.async.commit_group;");
}
// Monotone order-preserving float->u32 map (exact)
__device__ __forceinline__ unsigned f32_mono_u32(float x) {
    unsigned b = __float_as_uint(x);
    return b ^ (unsigned)(((int)b >> 31) | 0x80000000);
}

__global__ void __launch_bounds__(NTHREADS, 1)
crf_viterbi_kernel(const float* __restrict__ logits,
                   const int*   __restrict__ lens,
                   const float* __restrict__ trans,
                   float*       __restrict__ out)
{
    extern __shared__ char smraw[];
    SmemLayout& s = *reinterpret_cast<SmemLayout*>(smraw);

    const int b    = blockIdx.x;
    const int tid  = threadIdx.x;
    const int j    = tid & (KK - 1);   // output column
    const int q    = tid >> 7;         // quarter of i-range: [32q, 32q+32)
    const int lane = tid & 31;
    const int len  = lens[b];

    // ---- transC (column-major transitions, padded) ----
    for (int idx = tid; idx < KK * KK; idx += NTHREADS) {
        int i  = idx >> 7;
        int jj = idx & (KK - 1);
        s.transC[jj * TC_STRIDE + i] = trans[idx];
    }

    // ---- this thread's 32 transitions, packed as 16 f32x2 pairs ----
    unsigned long long t2[16];
    #pragma unroll
    for (int m = 0; m < 16; ++m) {
        float lo = trans[(q * 32 + 2 * m)     * KK + j];
        float hi = trans[(q * 32 + 2 * m + 1) * KK + j];
        asm("mov.b64 %0, {%1, %2};" : "=l"(t2[m]) : "f"(lo), "f"(hi));
    }

    // ---- init state = logits[b, 0, :] ----
    if (q == 0) {
        float v = logits[((size_t)b * TT) * KK + j];
        s.state[j] = v;
        g_state[((size_t)b * TT) * KK + j] = v;
    }

    // ---- prologue: stage logit rows 1..16 into buffer 0 ----
    {
        int row = 1 + (tid >> 5);
        if (row > TT - 1) row = TT - 1;
        const float* src = logits + ((size_t)b * TT + row) * KK + (tid & 31) * 4;
        cp_async16(smem_u32(&s.logit[0][tid >> 5][(tid & 31) * 4]), src);
        cp_commit();
    }
    __syncthreads();

    const unsigned sbase = smem_u32(&s.state[q * 32]);

    // ================= forward pass (value-only) =================
    for (int t = 1; t < len; ++t) {
        int rel = t - 1;
        if ((rel & 15) == 0) {
            int g = rel >> 4;
            int row = 1 + (g + 1) * 16 + (tid >> 5);
            if (row > TT - 1) row = TT - 1;
            const float* src = logits + ((size_t)b * TT + row) * KK + (tid & 31) * 4;
            cp_async16(smem_u32(&s.logit[(g + 1) & 1][tid >> 5][(tid & 31) * 4]), src);
            cp_commit();
            asm volatile("cp.async.wait_group 1;");
            __syncthreads();
        }

        // 32 candidates: 8x LDS.128 (broadcast), 16x add.rn.f32x2, FMNMX tree
        unsigned long long p0, p1, c0, c1;
        float acc0, acc1, acc2, acc3;
        asm volatile("ld.shared.v2.u64 {%0, %1}, [%2];"
                     : "=l"(p0), "=l"(p1) : "r"(sbase));
        asm("add.rn.f32x2 %0, %1, %2;" : "=l"(c0) : "l"(p0), "l"(t2[0]));
        asm("add.rn.f32x2 %0, %1, %2;" : "=l"(c1) : "l"(p1), "l"(t2[1]));
        asm("mov.b64 {%0, %1}, %2;" : "=f"(acc0), "=f"(acc1) : "l"(c0));
        asm("mov.b64 {%0, %1}, %2;" : "=f"(acc2), "=f"(acc3) : "l"(c1));
        #pragma unroll
        for (int u = 1; u < 8; ++u) {
            asm volatile("ld.shared.v2.u64 {%0, %1}, [%2];"
                         : "=l"(p0), "=l"(p1) : "r"(sbase + 16 * u));
            asm("add.rn.f32x2 %0, %1, %2;" : "=l"(c0) : "l"(p0), "l"(t2[2 * u]));
            asm("add.rn.f32x2 %0, %1, %2;" : "=l"(c1) : "l"(p1), "l"(t2[2 * u + 1]));
            float x0, x1, x2, x3;
            asm("mov.b64 {%0, %1}, %2;" : "=f"(x0), "=f"(x1) : "l"(c0));
            asm("mov.b64 {%0, %1}, %2;" : "=f"(x2), "=f"(x3) : "l"(c1));
            acc0 = fmaxf(acc0, x0);
            acc1 = fmaxf(acc1, x1);
            acc2 = fmaxf(acc2, x2);
            acc3 = fmaxf(acc3, x3);
        }
        float best = fmaxf(fmaxf(acc0, acc1), fmaxf(acc2, acc3));

        if (q) s.part[q][j] = best;
        __syncthreads();
        if (q == 0) {
            float v = fmaxf(fmaxf(best, s.part[1][j]),
                            fmaxf(s.part[2][j], s.part[3][j]))
                    + s.logit[(rel >> 4) & 1][rel & 15][j];
            s.state[j] = v;
            g_state[((size_t)b * TT + t) * KK + j] = v;
        }
        __syncthreads();
    }
    asm volatile("cp.async.wait_all;");

    // ---- last tag = argmax_j final state (first-index tie-break) ----
    if (tid == 0) {
        float bv = s.state[0];
        int bi = 0;
        for (int i = 1; i < KK; ++i) {
            float v = s.state[i];
            if (v > bv) { bv = v; bi = i; }
        }
        s.lasttag = bi;
    }
    __syncthreads();
    const int lt = s.lasttag;

    // tail fill: tags[t] = last_tag for t >= len-1
    for (int t = len - 1 + tid; t < TT; t += NTHREADS) s.tags[t] = lt;

    // ================= backtrack (recompute bp column per step) =================
    int cur = lt;
    for (int hi = len - 2; hi >= 0; hi -= 64) {
        int lo = hi - 63;
        if (lo < 0) lo = 0;
        int n = (hi - lo + 1) * KK;
        const float* src = g_state + ((size_t)b * TT + lo) * KK;
        for (int idx = tid * 4; idx < n; idx += NTHREADS * 4)
            *reinterpret_cast<float4*>(&s.block[idx]) =
                *reinterpret_cast<const float4*>(src + idx);
        __syncthreads();

        if (tid < 32) {
            for (int t = hi; t >= lo; --t) {
                float4 sv = *reinterpret_cast<const float4*>(
                    &s.block[(t - lo) * KK + 4 * lane]);
                float4 tv = *reinterpret_cast<const float4*>(
                    &s.transC[cur * TC_STRIDE + 4 * lane]);
                unsigned u0 = f32_mono_u32(sv.x + tv.x);
                unsigned u1 = f32_mono_u32(sv.y + tv.y);
                unsigned u2 = f32_mono_u32(sv.z + tv.z);
                unsigned u3 = f32_mono_u32(sv.w + tv.w);
                // local max with first-index preference (strict > keeps earlier)
                unsigned lm = u0; int li = 4 * lane;
                if (u1 > lm) { lm = u1; li = 4 * lane + 1; }
                if (u2 > lm) { lm = u2; li = 4 * lane + 2; }
                if (u3 > lm) { lm = u3; li = 4 * lane + 3; }
                unsigned gm = __reduce_max_sync(0xffffffffu, lm);
                unsigned cand = (lm == gm) ? (unsigned)li : 0xffffffffu;
                cur = (int)__reduce_min_sync(0xffffffffu, cand);
                if (lane == 0) s.tags[t] = cur;
            }
        }
        __syncthreads();
    }
    __syncthreads();  // covers len==1 path

    // ================= one-hot output =================
    const int w = tid >> 5;  // 16 warps: warp w writes rows t = w + 16*it
    float* ob = out + (size_t)b * TT * KK;
    for (int it = 0; it < TT / 16; ++it) {
        int t = it * 16 + w;
        int tg = s.tags[t];
        float4 v;
        v.x = (tg == 4 * lane + 0) ? 1.0f : 0.0f;
        v.y = (tg == 4 * lane + 1) ? 1.0f : 0.0f;
        v.z = (tg == 4 * lane + 2) ? 1.0f : 0.0f;
        v.w = (tg == 4 * lane + 3) ? 1.0f : 0.0f;
        *reinterpret_cast<float4*>(ob + (size_t)t * KK + 4 * lane) = v;
    }
}

extern "C" void kernel_launch(void* const* d_in, const int* in_sizes, int n_in,
                              void* d_out, int out_size) {
    const float* logits = (const float*)d_in[0];
    const int*   lens   = (const int*)d_in[1];
    const float* trans  = (const float*)d_in[2];
    float*       out    = (float*)d_out;

    cudaFuncSetAttribute(crf_viterbi_kernel,
                         cudaFuncAttributeMaxDynamicSharedMemorySize,
                         (int)sizeof(SmemLayout));
    crf_viterbi_kernel<<<BB, NTHREADS, sizeof(SmemLayout)>>>(logits, lens, trans, out);
}

// round 4
// speedup vs baseline: 1.2306x; 1.0643x over previous
#include <cuda_runtime.h>
#include <cstdint>

// CRF Viterbi decode: B=128, T=1024, K=128. One CTA (512 threads) per batch.
// Forward: warp-local layout — warp w owns j in [8w,8w+8); lane = q*8+jl;
// each thread partial-maxes 32 i's (f32x2 adds, transitions in regs), then
// 2x shfl.xor combines the 4 quarters inside the warp. Double-buffered state
// => ONE __syncthreads per step. Logits cp.async double-buffered. History ->
// 64MB scratch. Backtrack: warp 0 recomputes the needed argmax column with
// u32-monotone mapping + integer REDUX (exact first-index tie-break).

#define BB 128
#define TT 1024
#define KK 128
#define TC_STRIDE 132
#define SQ 36                // padded quarter stride (floats): conflict-free
#define NTHREADS 512

__device__ float g_state[(size_t)BB * TT * KK];

struct __align__(16) SmemLayout {
    float transC[KK * TC_STRIDE];   // transC[j*132 + i] = T[i][j]
    float spad[2][4 * SQ];          // double-buffered padded state
    float logit[2][16][KK];         // double-buffered logit staging
    float block[64 * KK];           // backtrack state-row staging
    int   tags[TT];
    int   lasttag;
};

__device__ __forceinline__ unsigned smem_u32(const void* p) {
    return (unsigned)__cvta_generic_to_shared(p);
}
__device__ __forceinline__ void cp_async16(unsigned dst, const void* src) {
    asm volatile("cp.async.cg.shared.global [%0], [%1], 16;" :: "r"(dst), "l"(src));
}
__device__ __forceinline__ unsigned f32_mono_u32(float x) {
    unsigned b = __float_as_uint(x);
    return b ^ (unsigned)(((int)b >> 31) | 0x80000000);
}

__global__ void __launch_bounds__(NTHREADS, 1)
crf_viterbi_kernel(const float* __restrict__ logits,
                   const int*   __restrict__ lens,
                   const float* __restrict__ trans,
                   float*       __restrict__ out)
{
    extern __shared__ char smraw[];
    SmemLayout& s = *reinterpret_cast<SmemLayout*>(smraw);

    const int b    = blockIdx.x;
    const int tid  = threadIdx.x;
    const int w    = tid >> 5;
    const int lane = tid & 31;
    const int q    = lane >> 3;        // i-quarter [32q, 32q+32)
    const int jl   = lane & 7;
    const int j    = w * 8 + jl;       // output column owned by this thread
    const int wq   = w >> 2;           // quarter that j lives in
    const int len  = lens[b];

    // ---- transC (column-major transitions, padded) ----
    for (int idx = tid; idx < KK * KK; idx += NTHREADS) {
        int i  = idx >> 7;
        int jj = idx & (KK - 1);
        s.transC[jj * TC_STRIDE + i] = trans[idx];
    }

    // ---- this thread's 32 transitions (i = 32q..32q+31, col j), 16 f32x2 ----
    unsigned long long t2[16];
    #pragma unroll
    for (int m = 0; m < 16; ++m) {
        float lo = trans[(q * 32 + 2 * m)     * KK + j];
        float hi = trans[(q * 32 + 2 * m + 1) * KK + j];
        asm("mov.b64 %0, {%1, %2};" : "=l"(t2[m]) : "f"(lo), "f"(hi));
    }

    // ---- init state = logits[b, 0, :] into spad[0] ----
    if (tid < KK) {
        float v = logits[((size_t)b * TT) * KK + tid];
        s.spad[0][(tid >> 5) * SQ + (tid & 31)] = v;
        g_state[((size_t)b * TT) * KK + tid] = v;
    }

    // ---- prologue: stage logit rows 1..16 into buffer 0 ----
    {
        int row = 1 + w;
        if (row > TT - 1) row = TT - 1;
        const float* src = logits + ((size_t)b * TT + row) * KK + lane * 4;
        cp_async16(smem_u32(&s.logit[0][w][lane * 4]), src);
        asm volatile("cp.async.commit_group;");
    }
    __syncthreads();

    const unsigned sb0 = smem_u32(&s.spad[0][q * SQ]);
    const unsigned sb1 = smem_u32(&s.spad[1][q * SQ]);
    int pr = 0;   // parity: spad[pr] holds current state

    // ================= forward pass (value-only) =================
    for (int t = 1; t < len; ++t) {
        const int rel = t - 1;
        if ((rel & 15) == 0) {
            int g = rel >> 4;
            int row = 1 + (g + 1) * 16 + w;
            if (row > TT - 1) row = TT - 1;
            const float* src = logits + ((size_t)b * TT + row) * KK + lane * 4;
            cp_async16(smem_u32(&s.logit[(g + 1) & 1][w][lane * 4]), src);
            asm volatile("cp.async.commit_group;");
            asm volatile("cp.async.wait_group 1;");
            __syncthreads();
        }

        const unsigned sbr = pr ? sb1 : sb0;
        const float lg = s.logit[(rel >> 4) & 1][rel & 15][j];  // prefetch

        // 32 candidates: 8x LDS(16B), 16x add.rn.f32x2, fmax tree (4 accums)
        unsigned long long p0, p1, c0, c1;
        float acc0, acc1, acc2, acc3;
        asm volatile("ld.shared.v2.u64 {%0, %1}, [%2];"
                     : "=l"(p0), "=l"(p1) : "r"(sbr));
        asm("add.rn.f32x2 %0, %1, %2;" : "=l"(c0) : "l"(p0), "l"(t2[0]));
        asm("add.rn.f32x2 %0, %1, %2;" : "=l"(c1) : "l"(p1), "l"(t2[1]));
        asm("mov.b64 {%0, %1}, %2;" : "=f"(acc0), "=f"(acc1) : "l"(c0));
        asm("mov.b64 {%0, %1}, %2;" : "=f"(acc2), "=f"(acc3) : "l"(c1));
        #pragma unroll
        for (int u = 1; u < 8; ++u) {
            asm volatile("ld.shared.v2.u64 {%0, %1}, [%2];"
                         : "=l"(p0), "=l"(p1) : "r"(sbr + 16 * u));
            asm("add.rn.f32x2 %0, %1, %2;" : "=l"(c0) : "l"(p0), "l"(t2[2 * u]));
            asm("add.rn.f32x2 %0, %1, %2;" : "=l"(c1) : "l"(p1), "l"(t2[2 * u + 1]));
            float x0, x1, x2, x3;
            asm("mov.b64 {%0, %1}, %2;" : "=f"(x0), "=f"(x1) : "l"(c0));
            asm("mov.b64 {%0, %1}, %2;" : "=f"(x2), "=f"(x3) : "l"(c1));
            acc0 = fmaxf(acc0, x0);
            acc1 = fmaxf(acc1, x1);
            acc2 = fmaxf(acc2, x2);
            acc3 = fmaxf(acc3, x3);
        }
        float best = fmaxf(fmaxf(acc0, acc1), fmaxf(acc2, acc3));

        // combine the 4 quarter-partials for this j inside the warp
        best = fmaxf(best, __shfl_xor_sync(0xffffffffu, best, 8));
        best = fmaxf(best, __shfl_xor_sync(0xffffffffu, best, 16));

        if (q == 0) {
            float v = best + lg;
            s.spad[pr ^ 1][wq * SQ + 8 * (w & 3) + jl] = v;
            g_state[((size_t)b * TT + t) * KK + j] = v;
        }
        pr ^= 1;
        __syncthreads();
    }
    asm volatile("cp.async.wait_all;");

    // ---- last tag = argmax_j final state (first-index tie-break) ----
    if (tid == 0) {
        float bv = s.spad[pr][0];
        int bi = 0;
        for (int i = 1; i < KK; ++i) {
            float v = s.spad[pr][(i >> 5) * SQ + (i & 31)];
            if (v > bv) { bv = v; bi = i; }
        }
        s.lasttag = bi;
    }
    __syncthreads();
    const int lt = s.lasttag;

    // tail fill: tags[t] = last_tag for t >= len-1
    for (int t = len - 1 + tid; t < TT; t += NTHREADS) s.tags[t] = lt;

    // ================= backtrack (recompute bp column per step) =================
    int cur = lt;
    for (int hi = len - 2; hi >= 0; hi -= 64) {
        int lo = hi - 63;
        if (lo < 0) lo = 0;
        int n = (hi - lo + 1) * KK;
        const float* src = g_state + ((size_t)b * TT + lo) * KK;
        for (int idx = tid * 4; idx < n; idx += NTHREADS * 4)
            *reinterpret_cast<float4*>(&s.block[idx]) =
                *reinterpret_cast<const float4*>(src + idx);
        __syncthreads();

        if (tid < 32) {
            float4 sv = *reinterpret_cast<const float4*>(
                &s.block[(hi - lo) * KK + 4 * lane]);
            for (int t = hi; t >= lo; --t) {
                float4 tv = *reinterpret_cast<const float4*>(
                    &s.transC[cur * TC_STRIDE + 4 * lane]);
                float4 svn;
                if (t > lo)
                    svn = *reinterpret_cast<const float4*>(
                        &s.block[(t - 1 - lo) * KK + 4 * lane]);
                unsigned u0 = f32_mono_u32(sv.x + tv.x);
                unsigned u1 = f32_mono_u32(sv.y + tv.y);
                unsigned u2 = f32_mono_u32(sv.z + tv.z);
                unsigned u3 = f32_mono_u32(sv.w + tv.w);
                unsigned lm = u0; int li = 4 * lane;
                if (u1 > lm) { lm = u1; li = 4 * lane + 1; }
                if (u2 > lm) { lm = u2; li = 4 * lane + 2; }
                if (u3 > lm) { lm = u3; li = 4 * lane + 3; }
                unsigned gm = __reduce_max_sync(0xffffffffu, lm);
                unsigned cand = (lm == gm) ? (unsigned)li : 0xffffffffu;
                cur = (int)__reduce_min_sync(0xffffffffu, cand);
                if (lane == 0) s.tags[t] = cur;
                sv = svn;
            }
        }
        __syncthreads();
    }
    __syncthreads();  // covers len==1 path

    // ================= one-hot output =================
    float* ob = out + (size_t)b * TT * KK;
    for (int it = 0; it < TT / 16; ++it) {
        int t = it * 16 + w;
        int tg = s.tags[t];
        float4 v;
        v.x = (tg == 4 * lane + 0) ? 1.0f : 0.0f;
        v.y = (tg == 4 * lane + 1) ? 1.0f : 0.0f;
        v.z = (tg == 4 * lane + 2) ? 1.0f : 0.0f;
        v.w = (tg == 4 * lane + 3) ? 1.0f : 0.0f;
        *reinterpret_cast<float4*>(ob + (size_t)t * KK + 4 * lane) = v;
    }
}

extern "C" void kernel_launch(void* const* d_in, const int* in_sizes, int n_in,
                              void* d_out, int out_size) {
    const float* logits = (const float*)d_in[0];
    const int*   lens   = (const int*)d_in[1];
    const float* trans  = (const float*)d_in[2];
    float*       out    = (float*)d_out;

    cudaFuncSetAttribute(crf_viterbi_kernel,
                         cudaFuncAttributeMaxDynamicSharedMemorySize,
                         (int)sizeof(SmemLayout));
    crf_viterbi_kernel<<<BB, NTHREADS, sizeof(SmemLayout)>>>(logits, lens, trans, out);
}